// round 1
// baseline (speedup 1.0000x reference)
#include <cuda_runtime.h>
#include <math.h>

// Problem constants
#define BATCH 8
#define FEAT  64
#define HH    512
#define WW    512
#define HW    (HH * WW)          // 262144
#define NSEG  33                 // ids 0..32 (0 = background)
#define NI    32                 // output instances 1..32

// Segment-max kernel config
#define WARPS1   16              // features per block (one warp per feature)
#define THREADS1 (WARPS1 * 32)   // 512
#define TILE     16384           // pixels per block
#define CHUNK    4096            // staged mask-id chunk
#define NTILES   (HW / TILE)     // 16
#define FGROUPS  (FEAT / WARPS1) // 4

// d_out layout: [0 .. 16384) vectors [B][NI][F], [16384 .. 49152) connections [B][4][NI(j)][NI(i)]
#define VEC_ELEMS (BATCH * NI * FEAT)

// ---------------------------------------------------------------------------
// Kernel 0: zero the vectors region (d_out is poisoned to 0xAA)
// ---------------------------------------------------------------------------
__global__ void init_vectors_kernel(float* __restrict__ out_vec) {
    int i = blockIdx.x * blockDim.x + threadIdx.x;
    if (i < VEC_ELEMS) out_vec[i] = 0.0f;
}

// ---------------------------------------------------------------------------
// Kernel 1: per-instance, per-feature segment max (+relu via 0-init)
//
// Grid: (NTILES, FGROUPS, BATCH). Block: 512 threads = 16 warps.
// Warp w handles feature f = fg*16 + w over the block's pixel tile.
// Per-thread private accumulators live in shared memory laid out
// s_acc[id * 512 + tid] -> bank = tid % 32 -> always conflict-free.
// ---------------------------------------------------------------------------
extern __shared__ char smem_raw[];

__global__ __launch_bounds__(THREADS1, 2)
void segmax_kernel(const float* __restrict__ enc,
                   const int*   __restrict__ masks,
                   float*       __restrict__ out_vec) {
    float* s_acc = (float*)smem_raw;                       // NSEG * 512 floats (67.5 KB)
    int*   s_ids = (int*)(smem_raw + NSEG * THREADS1 * 4); // CHUNK ints (16 KB)

    const int tid  = threadIdx.x;
    const int lane = tid & 31;
    const int w    = tid >> 5;

    const int tile = blockIdx.x;
    const int fg   = blockIdx.y;
    const int b    = blockIdx.z;
    const int f    = fg * WARPS1 + w;

    // Init private accumulators to 0 (this also implements the final relu:
    // negative segment maxima and empty segments both clamp to 0).
    #pragma unroll
    for (int r = 0; r < NSEG; r++) s_acc[r * THREADS1 + tid] = 0.0f;
    __syncthreads();

    const size_t pix_base = (size_t)b * HW + (size_t)tile * TILE;
    const float4* src = (const float4*)(enc + ((size_t)(b * FEAT + f)) * HW + (size_t)tile * TILE);
    const int4*   msk = (const int4*)(masks + pix_base);

    for (int c = 0; c < TILE / CHUNK; c++) {
        // Stage mask ids for this chunk (shared by all 16 warps/features)
        int4* sd = (int4*)s_ids;
        #pragma unroll
        for (int i = tid; i < CHUNK / 4; i += THREADS1)
            sd[i] = msk[c * (CHUNK / 4) + i];
        __syncthreads();

        const float4* s4  = src + c * (CHUNK / 4);
        const int4*   id4 = (const int4*)s_ids;

        #pragma unroll 4
        for (int g = 0; g < CHUNK / 4 / 32; g++) {   // 32 iterations
            const int idx = g * 32 + lane;
            const float4 v = s4[idx];
            const int4  id = id4[idx];

            float a;
            a = s_acc[id.x * THREADS1 + tid]; if (v.x > a) s_acc[id.x * THREADS1 + tid] = v.x;
            a = s_acc[id.y * THREADS1 + tid]; if (v.y > a) s_acc[id.y * THREADS1 + tid] = v.y;
            a = s_acc[id.z * THREADS1 + tid]; if (v.z > a) s_acc[id.z * THREADS1 + tid] = v.z;
            a = s_acc[id.w * THREADS1 + tid]; if (v.w > a) s_acc[id.w * THREADS1 + tid] = v.w;
        }
        __syncthreads();
    }

    // Warp-level reduce: the 32 lanes of warp w hold private maxima for feature f.
    // Positive floats compare correctly as signed ints -> int atomicMax on bit pattern.
    for (int id = 1; id < NSEG; id++) {
        float v = s_acc[id * THREADS1 + tid];
        #pragma unroll
        for (int off = 16; off; off >>= 1)
            v = fmaxf(v, __shfl_xor_sync(0xffffffffu, v, off));
        if (lane == 0 && v > 0.0f) {
            atomicMax((int*)&out_vec[((size_t)b * NI + (id - 1)) * FEAT + f],
                      __float_as_int(v));
        }
    }
}

// ---------------------------------------------------------------------------
// Kernel 2: pairwise relation MLP
// Grid: (4 j-chunks, 8 batches). Block: 256 threads -> lane = i, warp = j
// within the chunk. All weights + this batch's vectors staged in shared.
// ---------------------------------------------------------------------------
#define TH2 256

__global__ __launch_bounds__(TH2)
void mlp_kernel(const float* __restrict__ vec,
                const float* __restrict__ w1,
                const float* __restrict__ b1,
                const float* __restrict__ w2,
                const float* __restrict__ b2,
                float* __restrict__ out_conn) {
    __shared__ float s_w1[128 * 32];   // 16 KB, w1[k][m] = s_w1[k*32+m]
    __shared__ float s_v[NI * 65];     // padded stride 65 -> conflict-free lane-indexed reads
    __shared__ float s_w2[32 * 4];
    __shared__ float s_b1[32];
    __shared__ float s_b2[4];

    const int b   = blockIdx.y;
    const int jc  = blockIdx.x;
    const int tid = threadIdx.x;
    const int lane = tid & 31;
    const int wrp  = tid >> 5;

    for (int i = tid; i < 128 * 32; i += TH2) s_w1[i] = w1[i];
    for (int i = tid; i < NI * FEAT; i += TH2) {
        int r = i >> 6, c = i & 63;
        s_v[r * 65 + c] = vec[((size_t)b * NI + r) * FEAT + c];
    }
    if (tid < 128) s_w2[tid] = w2[tid];
    if (tid < 32)  s_b1[tid] = b1[tid];
    if (tid < 4)   s_b2[tid] = b2[tid];
    __syncthreads();

    const int i = lane;            // pair index i (first half of concat)
    const int j = jc * 8 + wrp;    // pair index j (second half of concat)

    float h[32];
    #pragma unroll
    for (int m = 0; m < 32; m++) h[m] = s_b1[m];

    #pragma unroll 4
    for (int k = 0; k < 64; k++) {
        const float va = s_v[i * 65 + k];   // conflict-free (stride 65)
        const float vb = s_v[j * 65 + k];   // uniform per warp -> broadcast
        #pragma unroll
        for (int m = 0; m < 32; m++) {
            h[m] += va * s_w1[k * 32 + m] + vb * s_w1[(64 + k) * 32 + m];
        }
    }

    #pragma unroll
    for (int c = 0; c < 4; c++) {
        float t = s_b2[c];
        #pragma unroll
        for (int m = 0; m < 32; m++) t += h[m] * s_w2[m * 4 + c];
        const float o = 1.0f / (1.0f + expf(-t));
        // connections[b, c, j, i]
        out_conn[(((size_t)b * 4 + c) * NI + j) * NI + i] = o;
    }
}

// ---------------------------------------------------------------------------
// Launch
// ---------------------------------------------------------------------------
extern "C" void kernel_launch(void* const* d_in, const int* in_sizes, int n_in,
                              void* d_out, int out_size) {
    const float* enc   = (const float*)d_in[0];
    const int*   masks = (const int*)d_in[1];
    const float* w1    = (const float*)d_in[2];
    const float* b1    = (const float*)d_in[3];
    const float* w2    = (const float*)d_in[4];
    const float* b2    = (const float*)d_in[5];

    float* out_vec  = (float*)d_out;
    float* out_conn = out_vec + VEC_ELEMS;

    static bool attr_set = false;
    const int smem_bytes = NSEG * THREADS1 * 4 + CHUNK * 4;  // 83968
    if (!attr_set) {
        cudaFuncSetAttribute(segmax_kernel,
                             cudaFuncAttributeMaxDynamicSharedMemorySize, smem_bytes);
        attr_set = true;
    }

    init_vectors_kernel<<<(VEC_ELEMS + 255) / 256, 256>>>(out_vec);

    dim3 grid1(NTILES, FGROUPS, BATCH);
    segmax_kernel<<<grid1, THREADS1, smem_bytes>>>(enc, masks, out_vec);

    dim3 grid2(4, BATCH);
    mlp_kernel<<<grid2, TH2>>>(out_vec, w1, b1, w2, b2, out_conn);
}

// round 2
// speedup vs baseline: 1.2308x; 1.2308x over previous
#include <cuda_runtime.h>
#include <math.h>

// Problem constants
#define BATCH 8
#define FEAT  64
#define HH    512
#define WW    512
#define HW    (HH * WW)          // 262144
#define NSEG  33                 // ids 0..32 (0 = background)
#define NI    32

// Segment-max persistent kernel config
#define THREADS1 512             // 16 warps = 16 features per (b,fg) group
#define TILEPX   2048            // pixels per work unit
#define NTILE    (HW / TILEPX)   // 128 tiles per (b,fg)
#define NBFG     (BATCH * 4)     // 32 (b, feature-group) groups
#define NU       (NBFG * NTILE)  // 4096 work units
#define NB       444             // 148 SMs * 3 CTAs

#define VEC_ELEMS (BATCH * NI * FEAT)   // 16384

// Per-(b,instance,feature) maxima as float bit patterns (nonneg -> int order ok).
// Statically zeroed; every call leaves it zeroed again (mlp kernel re-zeroes
// its batch slice after reading), so each call sees identical initial state.
__device__ int g_scratch[VEC_ELEMS];

// ---------------------------------------------------------------------------
// Kernel 1: persistent segment-max.
// Block = 512 threads (16 warps); warp w <-> feature f = fg*16 + w.
// Private per-thread accumulators in smem: s_acc[id*512 + tid] (bank=tid%32,
// always conflict-free). Work units (b, fg, tile) are evenly split across
// exactly NB blocks; accumulator flush happens only on (b,fg) change.
// ---------------------------------------------------------------------------
extern __shared__ char smem_raw[];

__global__ __launch_bounds__(THREADS1, 3)
void segmax_kernel(const float* __restrict__ enc,
                   const int*   __restrict__ masks) {
    float* s_acc = (float*)smem_raw;                          // 33*512 floats = 67584 B
    int*   s_ids = (int*)(smem_raw + NSEG * THREADS1 * 4);    // 2048 ints   =  8192 B

    const int tid  = threadIdx.x;
    const int lane = tid & 31;
    const int w    = tid >> 5;
    const int k    = blockIdx.x;

    const int s = (k * NU) / NB;
    const int e = ((k + 1) * NU) / NB;

    int cur = -1;
    int b = 0, f = 0;

    for (int u = s; u < e; ++u) {
        const int bfg = u >> 7;             // u / NTILE
        if (bfg != cur) {
            if (cur >= 0) {
                // flush: column tid is private to this thread; warp-reduce per id
                #pragma unroll
                for (int id = 1; id < NSEG; ++id) {
                    float v = s_acc[(id << 9) + tid];
                    #pragma unroll
                    for (int off = 16; off; off >>= 1)
                        v = fmaxf(v, __shfl_xor_sync(0xffffffffu, v, off));
                    if (lane == 0 && v > 0.0f)
                        atomicMax(&g_scratch[((b * NI) + (id - 1)) * FEAT + f],
                                  __float_as_int(v));
                }
            }
            #pragma unroll
            for (int r = 0; r < NSEG; ++r) s_acc[(r << 9) + tid] = 0.0f;
            cur = bfg;
            b = bfg >> 2;
            f = ((bfg & 3) << 4) | w;
        }
        const int tile = u & (NTILE - 1);

        // Stage mask ids for this tile (premultiplied by 512 = row stride).
        __syncthreads();   // prior tile's s_ids consumers are done
        {
            const int4 m = ((const int4*)(masks + (size_t)b * HW + tile * TILEPX))[tid];
            ((int4*)s_ids)[tid] = make_int4(m.x << 9, m.y << 9, m.z << 9, m.w << 9);
        }
        __syncthreads();

        const float4* src4 = (const float4*)enc
                           + (size_t)(b * FEAT + f) * (HW / 4)
                           + tile * (TILEPX / 4);
        const int4* id4 = (const int4*)s_ids;

        #pragma unroll 4
        for (int g = 0; g < TILEPX / 4 / 32; ++g) {   // 16 iterations
            const int idx = g * 32 + lane;
            const float4 v = src4[idx];
            const int4  o = id4[idx];
            float a;
            a = s_acc[o.x + tid]; if (v.x > a) s_acc[o.x + tid] = v.x;
            a = s_acc[o.y + tid]; if (v.y > a) s_acc[o.y + tid] = v.y;
            a = s_acc[o.z + tid]; if (v.z > a) s_acc[o.z + tid] = v.z;
            a = s_acc[o.w + tid]; if (v.w > a) s_acc[o.w + tid] = v.w;
        }
    }

    // final flush
    #pragma unroll
    for (int id = 1; id < NSEG; ++id) {
        float v = s_acc[(id << 9) + tid];
        #pragma unroll
        for (int off = 16; off; off >>= 1)
            v = fmaxf(v, __shfl_xor_sync(0xffffffffu, v, off));
        if (lane == 0 && v > 0.0f)
            atomicMax(&g_scratch[((b * NI) + (id - 1)) * FEAT + f],
                      __float_as_int(v));
    }
}

// ---------------------------------------------------------------------------
// Kernel 2: collapsed relation MLP (no nonlinearity between layers!):
//   out[b,c,j,i] = sigmoid( v_i . (W1a W2) + v_j . (W1b W2) + (b1 W2 + b2) )
// One block per batch. Also copies vectors to d_out and re-zeroes scratch.
// ---------------------------------------------------------------------------
#define TH2 256

__global__ __launch_bounds__(TH2)
void mlp_kernel(const float* __restrict__ w1,
                const float* __restrict__ b1,
                const float* __restrict__ w2,
                const float* __restrict__ b2,
                float* __restrict__ out_vec,
                float* __restrict__ out_conn) {
    __shared__ float s_m1[FEAT * 4];     // (W1a W2): [64][4]
    __shared__ float s_m2[FEAT * 4];     // (W1b W2): [64][4]
    __shared__ float s_c0[4];            // b1 W2 + b2
    __shared__ float s_v[NI * 65];       // padded: bank = (i*65+k)%32 varies with i
    __shared__ float s_P[NI * 4];
    __shared__ float s_Q[NI * 4];

    const int b   = blockIdx.x;
    const int tid = threadIdx.x;

    // Fold weights: s_m1[k*4+c] = sum_m w1[k][m] * w2[m][c]
    {
        const int kk = tid >> 2, c = tid & 3;
        float a1 = 0.0f, a2 = 0.0f;
        #pragma unroll 8
        for (int m = 0; m < 32; ++m) {
            const float w2v = w2[m * 4 + c];
            a1 += w1[kk * 32 + m] * w2v;
            a2 += w1[(64 + kk) * 32 + m] * w2v;
        }
        s_m1[tid] = a1;
        s_m2[tid] = a2;
        if (tid < 4) {
            float a = b2[tid];
            #pragma unroll 8
            for (int m = 0; m < 32; ++m) a += b1[m] * w2[m * 4 + tid];
            s_c0[tid] = a;
        }
    }

    // Stage this batch's vectors, emit them to d_out, and re-zero scratch.
    // Only this block reads batch b's slice, so the zero is race-free.
    for (int t = tid; t < NI * FEAT; t += TH2) {
        const float vv = __int_as_float(g_scratch[b * NI * FEAT + t]);
        s_v[(t >> 6) * 65 + (t & 63)] = vv;
        out_vec[(size_t)b * NI * FEAT + t] = vv;
        g_scratch[b * NI * FEAT + t] = 0;
    }
    __syncthreads();

    // P[i][c] = v_i . m1col_c ;  Q[j][c] = v_j . m2col_c
    if (tid < 128) {
        const int i = tid >> 2, c = tid & 3;
        float p = 0.0f;
        #pragma unroll 8
        for (int kk = 0; kk < FEAT; ++kk) p += s_v[i * 65 + kk] * s_m1[kk * 4 + c];
        s_P[tid] = p;
    } else {
        const int t2 = tid - 128;
        const int j = t2 >> 2, c = t2 & 3;
        float q = 0.0f;
        #pragma unroll 8
        for (int kk = 0; kk < FEAT; ++kk) q += s_v[j * 65 + kk] * s_m2[kk * 4 + c];
        s_Q[t2] = q;
    }
    __syncthreads();

    // out[b, c, j, i] = sigmoid(P[i][c] + Q[j][c] + c0[c])
    #pragma unroll
    for (int r = 0; r < 16; ++r) {
        const int o = r * TH2 + tid;        // o = c*1024 + j*32 + i
        const int c = o >> 10;
        const int j = (o >> 5) & 31;
        const int i = o & 31;
        const float t = s_P[i * 4 + c] + s_Q[j * 4 + c] + s_c0[c];
        out_conn[(size_t)b * 4096 + o] = 1.0f / (1.0f + expf(-t));
    }
}

// ---------------------------------------------------------------------------
// Launch
// ---------------------------------------------------------------------------
extern "C" void kernel_launch(void* const* d_in, const int* in_sizes, int n_in,
                              void* d_out, int out_size) {
    const float* enc   = (const float*)d_in[0];
    const int*   masks = (const int*)d_in[1];
    const float* w1    = (const float*)d_in[2];
    const float* b1    = (const float*)d_in[3];
    const float* w2    = (const float*)d_in[4];
    const float* b2    = (const float*)d_in[5];

    float* out_vec  = (float*)d_out;
    float* out_conn = out_vec + VEC_ELEMS;

    static bool attr_set = false;
    const int smem_bytes = NSEG * THREADS1 * 4 + TILEPX * 4;  // 75776
    if (!attr_set) {
        cudaFuncSetAttribute(segmax_kernel,
                             cudaFuncAttributeMaxDynamicSharedMemorySize, smem_bytes);
        attr_set = true;
    }

    segmax_kernel<<<NB, THREADS1, smem_bytes>>>(enc, masks);
    mlp_kernel<<<BATCH, TH2>>>(w1, b1, w2, b2, out_vec, out_conn);
}